// round 8
// baseline (speedup 1.0000x reference)
#include <cuda_runtime.h>
#include <cstdint>
#include <math.h>

// Problem constants
#define BB   8
#define LL   128
#define SS   100
#define TT   100
#define QD   512
#define FD   2048
#define HD   512
#define OD   512

// Scratch (device globals; no allocation APIs allowed)
__device__ float g_q[BB * LL * HD];
__device__ float g_key[BB * (SS + TT) * HD];
__device__ float g_ctx[BB * LL * HD];
__device__ float g_wts[BB * 200 * 128];
__device__ float g_wqT[HD * QD];
__device__ float g_wsT[HD * FD];
__device__ float g_woT[OD * (QD + HD)];

// ---------------------------------------------------------------------------
__device__ __forceinline__ uint32_t s2u(const void* p) {
    uint32_t a;
    asm("{ .reg .u64 t; cvta.to.shared.u64 t, %1; cvt.u32.u64 %0, t; }" : "=r"(a) : "l"(p));
    return a;
}
__device__ __forceinline__ void cp16(uint32_t dst, const void* src) {
    asm volatile("cp.async.cg.shared.global [%0], [%1], 16;" :: "r"(dst), "l"(src));
}
#define CP_COMMIT()  asm volatile("cp.async.commit_group;" ::: "memory")
#define CP_WAITG(n)  asm volatile("cp.async.wait_group %0;" :: "n"(n) : "memory")

#define LDSM4(r, a) \
    asm volatile("ldmatrix.sync.aligned.m8n8.x4.shared.b16 {%0,%1,%2,%3}, [%4];" \
        : "=r"((r)[0]), "=r"((r)[1]), "=r"((r)[2]), "=r"((r)[3]) : "r"(a))

#define MMA_TF32(d, a, b0, b1) \
    asm volatile("mma.sync.aligned.m16n8k8.row.col.f32.tf32.tf32.f32 " \
        "{%0,%1,%2,%3}, {%4,%5,%6,%7}, {%8,%9}, {%0,%1,%2,%3};" \
        : "+f"((d)[0]), "+f"((d)[1]), "+f"((d)[2]), "+f"((d)[3]) \
        : "r"((a)[0]), "r"((a)[1]), "r"((a)[2]), "r"((a)[3]), "r"(b0), "r"(b1))

extern __shared__ __align__(128) float dynsm[];

// ---------------------------------------------------------------------------
// Fused weight transposes + tf32 RN rounding (one launch, 3 segments), N = 512
// ---------------------------------------------------------------------------
__global__ __launch_bounds__(256) void transposeAll(
    const float* __restrict__ Wq, float* __restrict__ wqT,
    const float* __restrict__ Ws, float* __restrict__ wsT,
    const float* __restrict__ Wo, float* __restrict__ woT)
{
    __shared__ float t[32][33];
    int bid = blockIdx.x;
    const float* W; float* WT; int K;
    if (bid < 256)       { W = Wq; WT = wqT; K = 512;  }
    else if (bid < 1280) { W = Ws; WT = wsT; K = 2048; bid -= 256;  }
    else                 { W = Wo; WT = woT; K = 1024; bid -= 1280; }
    int k0 = (bid >> 4) * 32, n0 = (bid & 15) * 32;
    int x = threadIdx.x & 31, y = threadIdx.x >> 5;
#pragma unroll
    for (int i = 0; i < 32; i += 8)
        t[y + i][x] = W[(long)(k0 + y + i) * 512 + n0 + x];
    __syncthreads();
#pragma unroll
    for (int i = 0; i < 32; i += 8) {
        float v = t[x][y + i];
        asm("cvt.rna.tf32.f32 %0, %0;" : "+f"(v));
        WT[(long)(n0 + y + i) * K + k0 + x] = v;
    }
}

__global__ __launch_bounds__(256) void initOut(float* __restrict__ out,
                                               const float* __restrict__ bias) {
    int i = blockIdx.x * 256 + threadIdx.x;
    float4 b = ((const float4*)bias)[i & 127];
    ((float4*)out)[i] = b;
}

// ---------------------------------------------------------------------------
// tf32 mma.sync GEMM (unchanged from R7): C[M,512] (+)= A @ WT^T [+ bias]
// ---------------------------------------------------------------------------
struct GD {
    const float* A0; const float* A1;
    int rowSplit;
    int lda;
    const float* WT;
    int ldw;
    const float* bias;
    float* C;
    int K;
    int Mreal;
    int atomicFlag;
};

#define STG_BYTES 16384u
#define ABASE(s) ((s) * STG_BYTES)
#define BBASE(s) ((s) * STG_BYTES + 8192u)
#define DSMEM_G  49152

__global__ __launch_bounds__(128) void gemm_mma(GD ga, GD gb, int tilesA)
{
    const bool first = (blockIdx.x < (unsigned)tilesA);
    GD g = first ? ga : gb;
    const int lbid = first ? blockIdx.x : blockIdx.x - tilesA;

    const int bm = (lbid >> 3) * 64;
    const int bn = (lbid & 7) * 64;
    const int tid  = threadIdx.x;
    const int lane = tid & 31;
    const int wid  = tid >> 5;
    const int wm   = (wid & 1) * 32;
    const int wn   = (wid >> 1) * 32;
    const int T = g.K >> 5;
    const int Mlast = g.Mreal - 1;

    const uint32_t smem = s2u(dynsm);

    const int lr     = lane & 7;
    const int rowoff = ((lane >> 3) & 1) * 8;
    const int coff   = lane >> 4;
    const int arow   = wm + rowoff + lr;
    const int brow   = wn + rowoff + lr;

    float acc[2][4][4];
#pragma unroll
    for (int mi = 0; mi < 2; mi++)
#pragma unroll
        for (int ni = 0; ni < 4; ni++)
#pragma unroll
            for (int j = 0; j < 4; j++) acc[mi][ni][j] = 0.f;

    auto issue_tile = [&](int t, int s) {
        const int k0 = t << 5;
#pragma unroll
        for (int i = 0; i < 4; i++) {
            int idx = tid + (i << 7);
            int r = idx >> 3, c = idx & 7;
            uint32_t dst = smem + ABASE(s) + (uint32_t)((r << 3) + (c ^ (r & 7))) * 16u;
            int gr = bm + r; if (gr > Mlast) gr = Mlast;
            const float* p = (gr < g.rowSplit)
                ? g.A0 + (long)gr * g.lda
                : g.A1 + (long)(gr - g.rowSplit) * g.lda;
            cp16(dst, p + k0 + c * 4);
        }
#pragma unroll
        for (int i = 0; i < 4; i++) {
            int idx = tid + (i << 7);
            int r = idx >> 3, c = idx & 7;
            uint32_t dst = smem + BBASE(s) + (uint32_t)((r << 3) + (c ^ (r & 7))) * 16u;
            cp16(dst, g.WT + (long)(bn + r) * g.ldw + k0 + c * 4);
        }
    };

    issue_tile(0, 0); CP_COMMIT();
    issue_tile(1, 1); CP_COMMIT();

    int s = 0;
    for (int t = 0; t < T; t++) {
        CP_WAITG(1);
        __syncthreads();
        int sn = s + 2; if (sn >= 3) sn -= 3;
        if (t + 2 < T) issue_tile(t + 2, sn);
        CP_COMMIT();

        const uint32_t ab = smem + ABASE(s);
        const uint32_t bb = smem + BBASE(s);
#pragma unroll
        for (int ks = 0; ks < 4; ks++) {
            uint32_t a[2][4], bf[2][4];
#pragma unroll
            for (int mi = 0; mi < 2; mi++) {
                uint32_t ad = ab + (uint32_t)(arow + mi * 16) * 128u
                                 + (uint32_t)(((ks << 1) + coff) ^ lr) * 16u;
                LDSM4(a[mi], ad);
            }
#pragma unroll
            for (int ng = 0; ng < 2; ng++) {
                uint32_t bd = bb + (uint32_t)(brow + ng * 16) * 128u
                                 + (uint32_t)(((ks << 1) + coff) ^ lr) * 16u;
                LDSM4(bf[ng], bd);
            }
#pragma unroll
            for (int mi = 0; mi < 2; mi++)
#pragma unroll
                for (int j = 0; j < 4; j++)
                    asm("cvt.rna.tf32.f32 %0, %0;" : "+r"(a[mi][j]));
#pragma unroll
            for (int mi = 0; mi < 2; mi++)
#pragma unroll
                for (int ni = 0; ni < 4; ni++) {
                    int ng = ni >> 1, sel = ni & 1;
                    MMA_TF32(acc[mi][ni], a[mi], bf[ng][sel], bf[ng][sel + 2]);
                }
        }
        if (++s >= 3) s -= 3;
    }

    const int r0 = bm + wm + (lane >> 2);
    const int cb = bn + wn + 2 * (lane & 3);
    if (!g.atomicFlag) {
#pragma unroll
        for (int ni = 0; ni < 4; ni++) {
            int col = cb + ni * 8;
            float2 bv = *(const float2*)&g.bias[col];
#pragma unroll
            for (int mi = 0; mi < 2; mi++) {
                int r = r0 + mi * 16;
                if (r < g.Mreal) {
                    float2 v0 = { acc[mi][ni][0] + bv.x, acc[mi][ni][1] + bv.y };
                    *(float2*)&g.C[(long)r * 512 + col] = v0;
                }
                if (r + 8 < g.Mreal) {
                    float2 v1 = { acc[mi][ni][2] + bv.x, acc[mi][ni][3] + bv.y };
                    *(float2*)&g.C[(long)(r + 8) * 512 + col] = v1;
                }
            }
        }
    } else {
#pragma unroll
        for (int ni = 0; ni < 4; ni++) {
            int col = cb + ni * 8;
#pragma unroll
            for (int mi = 0; mi < 2; mi++) {
                int r = r0 + mi * 16;
                if (r < g.Mreal) {
                    atomicAdd(&g.C[(long)r * 512 + col],     acc[mi][ni][0]);
                    atomicAdd(&g.C[(long)r * 512 + col + 1], acc[mi][ni][1]);
                }
                if (r + 8 < g.Mreal) {
                    atomicAdd(&g.C[(long)(r + 8) * 512 + col],     acc[mi][ni][2]);
                    atomicAdd(&g.C[(long)(r + 8) * 512 + col + 1], acc[mi][ni][3]);
                }
            }
        }
    }
}

// ---------------------------------------------------------------------------
// attn_w: scores (smem-staged keys, coalesced) + factorized softmax.
//   Grid (16 ltiles, 8 b), 512 threads. Writes signed weights to
//   g_wts[b][j][l]  (j<100: +ws, j>=100: -wt, both scaled by 1/sqrt(2)).
// Dyn smem: q[8*512] | kbuf[2][200*36] | ssc[8*200]  = 80384 B
// ---------------------------------------------------------------------------
#define AW_Q    0
#define AW_KB   4096
#define AW_SSC  (4096 + 14400)
#define DSMEM_W ((4096 + 14400 + 1600) * 4)

__global__ __launch_bounds__(512) void attn_w(
    const float* __restrict__ gq, const float* __restrict__ gkey,
    float* __restrict__ gwts)
{
    float* qsm = dynsm + AW_Q;
    float* kb  = dynsm + AW_KB;
    float* ssc = dynsm + AW_SSC;

    const int b  = blockIdx.y;
    const int l0 = blockIdx.x * 8;
    const int tid = threadIdx.x;

    const float* keyS = gkey + (long)(b * SS) * HD;
    const float* keyT = gkey + (long)(BB * SS + b * TT) * HD;

    // load q (8 x 512)
#pragma unroll
    for (int i = 0; i < 2; i++) {
        int idx = tid + (i << 9);
        int l = idx >> 7, c4 = idx & 127;
        ((float4*)qsm)[l * 128 + c4] =
            __ldg((const float4*)(gq + (long)(b * LL + l0 + l) * HD) + c4);
    }

    const uint32_t kbu = s2u(kb);
    auto issue = [&](int t, int s) {
        const int k0 = t << 5;
        for (int i = tid; i < 1600; i += 512) {
            int r = i >> 3, c4 = i & 7;
            uint32_t dst = kbu + (uint32_t)(s * 28800 + r * 144 + c4 * 16);
            const float* p = (r < SS) ? keyS + (long)r * HD
                                      : keyT + (long)(r - SS) * HD;
            cp16(dst, p + k0 + c4 * 4);
        }
    };

    const int j = tid >> 1;         // key row (pairs of lanes)
    const int h = tid & 1;          // k-half within tile

    float acc[8];
#pragma unroll
    for (int l = 0; l < 8; l++) acc[l] = 0.f;

    issue(0, 0); CP_COMMIT();
    int buf = 0;
    for (int t = 0; t < 16; t++) {
        if (t + 1 < 16) { issue(t + 1, buf ^ 1); CP_COMMIT(); CP_WAITG(1); }
        else            { CP_WAITG(0); }
        __syncthreads();
        if (j < 200) {
            const float* kr = kb + buf * 7200 + j * 36 + h * 16;
            const float* qp = qsm + t * 32 + h * 16;
#pragma unroll
            for (int k4 = 0; k4 < 4; k4++) {
                float4 kv = *(const float4*)(kr + k4 * 4);
#pragma unroll
                for (int l = 0; l < 8; l++) {
                    float4 q4 = *(const float4*)(qp + l * 512 + k4 * 4);
                    acc[l] += kv.x * q4.x + kv.y * q4.y + kv.z * q4.z + kv.w * q4.w;
                }
            }
        }
        __syncthreads();
        buf ^= 1;
    }

    // pair-combine (k-halves) and publish scores
#pragma unroll
    for (int l = 0; l < 8; l++) {
        float v = acc[l] + __shfl_xor_sync(0xffffffffu, acc[l], 1);
        if (h == 0 && j < 200) ssc[l * 200 + j] = v;
    }
    __syncthreads();

    // factorized softmax: warps 0..7, warp = l
    const int wid  = tid >> 5;
    const int lane = tid & 31;
    if (wid < 8) {
        const int l = wid;
        const float sc1 = 1.0f / 32.0f;
        const float rs2 = 0.70710678118654752f;
        float* wrow = gwts + ((long)b * 200) * 128 + l0 + l;

        float vb[4], m = -1e30f;
#pragma unroll
        for (int ii = 0; ii < 4; ii++) {
            int jj = lane + 32 * ii;
            vb[ii] = (jj < SS) ? ssc[l * 200 + jj] * sc1 : -1e30f;
            m = fmaxf(m, vb[ii]);
        }
#pragma unroll
        for (int off = 16; off; off >>= 1) m = fmaxf(m, __shfl_xor_sync(0xffffffffu, m, off));
        float sum = 0.f;
#pragma unroll
        for (int ii = 0; ii < 4; ii++) {
            int jj = lane + 32 * ii;
            if (jj < SS) { vb[ii] = __expf(vb[ii] - m); sum += vb[ii]; }
        }
#pragma unroll
        for (int off = 16; off; off >>= 1) sum += __shfl_xor_sync(0xffffffffu, sum, off);
        float inv = rs2 / sum;
#pragma unroll
        for (int ii = 0; ii < 4; ii++) {
            int jj = lane + 32 * ii;
            if (jj < SS) wrow[(long)jj * 128] = vb[ii] * inv;
        }

        m = -1e30f;
#pragma unroll
        for (int ii = 0; ii < 4; ii++) {
            int jj = lane + 32 * ii;
            vb[ii] = (jj < TT) ? -ssc[l * 200 + SS + jj] * sc1 : -1e30f;
            m = fmaxf(m, vb[ii]);
        }
#pragma unroll
        for (int off = 16; off; off >>= 1) m = fmaxf(m, __shfl_xor_sync(0xffffffffu, m, off));
        sum = 0.f;
#pragma unroll
        for (int ii = 0; ii < 4; ii++) {
            int jj = lane + 32 * ii;
            if (jj < TT) { vb[ii] = __expf(vb[ii] - m); sum += vb[ii]; }
        }
#pragma unroll
        for (int off = 16; off; off >>= 1) sum += __shfl_xor_sync(0xffffffffu, sum, off);
        inv = -rs2 / sum;                       // minus folded in
#pragma unroll
        for (int ii = 0; ii < 4; ii++) {
            int jj = lane + 32 * ii;
            if (jj < TT) wrow[(long)(SS + jj) * 128] = vb[ii] * inv;
        }
    }
}

// ---------------------------------------------------------------------------
// attn_ctx: ctx[b, l0..l0+32, c0..c0+64] = sum_j w[j][l] * key[j][c]
//   Grid (8 coltiles, 4 ltiles, 8 b), 256 threads, weights tile in smem.
// ---------------------------------------------------------------------------
__global__ __launch_bounds__(256) void attn_ctx(
    const float* __restrict__ gwts, const float* __restrict__ gkey,
    float* __restrict__ gctx)
{
    __shared__ __align__(16) float ws[200 * 36];

    const int c0 = blockIdx.x * 64;
    const int l0 = blockIdx.y * 32;
    const int b  = blockIdx.z;
    const int tid = threadIdx.x;

    // load weights [200][32] (rows padded to 36)
    for (int i = tid; i < 1600; i += 256) {
        int r = i >> 3, c4 = i & 7;
        *(float4*)&ws[r * 36 + c4 * 4] =
            *(const float4*)(gwts + ((long)b * 200 + r) * 128 + l0 + c4 * 4);
    }
    __syncthreads();

    const int ci = tid & 15;         // col4 index (64 cols)
    const int lg = tid >> 4;         // 0..15, covers l = lg*2, lg*2+1
    const float* pS = gkey + (long)(b * SS) * HD + c0 + ci * 4;
    const float* pT = gkey + (long)(BB * SS + b * TT) * HD + c0 + ci * 4;

    float4 a0 = {0,0,0,0}, a1 = {0,0,0,0};
#pragma unroll 4
    for (int jj = 0; jj < SS; jj++) {
        float4 kv = __ldg((const float4*)(pS + (long)jj * HD));
        float w0 = ws[jj * 36 + lg * 2];
        float w1 = ws[jj * 36 + lg * 2 + 1];
        a0.x += w0 * kv.x; a0.y += w0 * kv.y; a0.z += w0 * kv.z; a0.w += w0 * kv.w;
        a1.x += w1 * kv.x; a1.y += w1 * kv.y; a1.z += w1 * kv.z; a1.w += w1 * kv.w;
    }
#pragma unroll 4
    for (int jj = 0; jj < TT; jj++) {
        float4 kv = __ldg((const float4*)(pT + (long)jj * HD));
        float w0 = ws[(SS + jj) * 36 + lg * 2];
        float w1 = ws[(SS + jj) * 36 + lg * 2 + 1];
        a0.x += w0 * kv.x; a0.y += w0 * kv.y; a0.z += w0 * kv.z; a0.w += w0 * kv.w;
        a1.x += w1 * kv.x; a1.y += w1 * kv.y; a1.z += w1 * kv.z; a1.w += w1 * kv.w;
    }

    float* base = gctx + (long)(b * LL + l0 + lg * 2) * HD + c0 + ci * 4;
    *(float4*)base        = a0;
    *(float4*)(base + HD) = a1;
}

// ---------------------------------------------------------------------------
extern "C" void kernel_launch(void* const* d_in, const int* in_sizes, int n_in,
                              void* d_out, int out_size)
{
    const float* query = (const float*)d_in[0];
    const float* src   = (const float*)d_in[1];
    const float* trg   = (const float*)d_in[2];
    const float* Wq    = (const float*)d_in[3];
    const float* bq    = (const float*)d_in[4];
    const float* Ws    = (const float*)d_in[5];
    const float* bs    = (const float*)d_in[6];
    const float* Wo    = (const float*)d_in[7];
    const float* bo    = (const float*)d_in[8];
    float* out = (float*)d_out;

    float *qbuf, *keybuf, *ctxbuf, *wtsbuf, *wqT, *wsT, *woT;
    cudaGetSymbolAddress((void**)&qbuf,   g_q);
    cudaGetSymbolAddress((void**)&keybuf, g_key);
    cudaGetSymbolAddress((void**)&ctxbuf, g_ctx);
    cudaGetSymbolAddress((void**)&wtsbuf, g_wts);
    cudaGetSymbolAddress((void**)&wqT,    g_wqT);
    cudaGetSymbolAddress((void**)&wsT,    g_wsT);
    cudaGetSymbolAddress((void**)&woT,    g_woT);

    cudaFuncSetAttribute(gemm_mma, cudaFuncAttributeMaxDynamicSharedMemorySize, DSMEM_G);
    cudaFuncSetAttribute(attn_w,   cudaFuncAttributeMaxDynamicSharedMemorySize, DSMEM_W);

    // Weight transposes (tf32 RN pre-rounding) + bias pre-init of out
    transposeAll<<<1792, 256>>>(Wq, wqT, Ws, wsT, Wo, woT);
    initOut<<<512, 256>>>(out, bo);

    // Fused key-proj (first: long K) + q-proj
    GD dKey = { src,   trg,   BB * SS, FD, wsT, FD, bs, keybuf, FD, BB * (SS + TT), 0 };
    GD dQ   = { query, query, 1 << 30, QD, wqT, QD, bq, qbuf,   QD, BB * LL, 0 };
    gemm_mma<<<26 * 8 + 16 * 8, 128, DSMEM_G>>>(dKey, dQ, 26 * 8);

    // Attention middle: weights, then ctx
    attn_w<<<dim3(16, 8), 512, DSMEM_W>>>(qbuf, keybuf, wtsbuf);
    attn_ctx<<<dim3(8, 4, 8), 256>>>(wtsbuf, keybuf, ctxbuf);

    // Out-proj as split-K at the concat boundary
    GD dO1 = { query,  query,  1 << 30, QD, woT,      QD + HD, 0, out, QD, BB * LL, 1 };
    GD dO2 = { ctxbuf, ctxbuf, 1 << 30, HD, woT + QD, QD + HD, 0, out, HD, BB * LL, 1 };
    gemm_mma<<<256, 128, DSMEM_G>>>(dO1, dO2, 128);
}

// round 9
// speedup vs baseline: 1.0365x; 1.0365x over previous
#include <cuda_runtime.h>
#include <cstdint>
#include <math.h>

// Problem constants
#define BB   8
#define LL   128
#define SS   100
#define TT   100
#define QD   512
#define FD   2048
#define HD   512
#define OD   512

// Scratch (device globals; no allocation APIs allowed)
__device__ float g_q[BB * LL * HD];
__device__ float g_key[BB * (SS + TT) * HD];
__device__ float g_ctx[BB * LL * HD];
__device__ float g_sc[BB * LL * 200];
__device__ float g_wts[BB * 200 * 128];
__device__ float g_wqT[HD * QD];
__device__ float g_wsT[HD * FD];
__device__ float g_woT[OD * (QD + HD)];

// ---------------------------------------------------------------------------
__device__ __forceinline__ uint32_t s2u(const void* p) {
    uint32_t a;
    asm("{ .reg .u64 t; cvta.to.shared.u64 t, %1; cvt.u32.u64 %0, t; }" : "=r"(a) : "l"(p));
    return a;
}
__device__ __forceinline__ void cp16(uint32_t dst, const void* src) {
    asm volatile("cp.async.cg.shared.global [%0], [%1], 16;" :: "r"(dst), "l"(src));
}
#define CP_COMMIT()  asm volatile("cp.async.commit_group;" ::: "memory")
#define CP_WAITG(n)  asm volatile("cp.async.wait_group %0;" :: "n"(n) : "memory")

#define LDSM4(r, a) \
    asm volatile("ldmatrix.sync.aligned.m8n8.x4.shared.b16 {%0,%1,%2,%3}, [%4];" \
        : "=r"((r)[0]), "=r"((r)[1]), "=r"((r)[2]), "=r"((r)[3]) : "r"(a))

#define MMA_TF32(d, a, b0, b1) \
    asm volatile("mma.sync.aligned.m16n8k8.row.col.f32.tf32.tf32.f32 " \
        "{%0,%1,%2,%3}, {%4,%5,%6,%7}, {%8,%9}, {%0,%1,%2,%3};" \
        : "+f"((d)[0]), "+f"((d)[1]), "+f"((d)[2]), "+f"((d)[3]) \
        : "r"((a)[0]), "r"((a)[1]), "r"((a)[2]), "r"((a)[3]), "r"(b0), "r"(b1))

extern __shared__ __align__(128) float dynsm[];

// ---------------------------------------------------------------------------
// Fused weight transposes + tf32 RN rounding (one launch, 3 segments), N = 512
// ---------------------------------------------------------------------------
__global__ __launch_bounds__(256) void transposeAll(
    const float* __restrict__ Wq, float* __restrict__ wqT,
    const float* __restrict__ Ws, float* __restrict__ wsT,
    const float* __restrict__ Wo, float* __restrict__ woT)
{
    __shared__ float t[32][33];
    int bid = blockIdx.x;
    const float* W; float* WT; int K;
    if (bid < 256)       { W = Wq; WT = wqT; K = 512;  }
    else if (bid < 1280) { W = Ws; WT = wsT; K = 2048; bid -= 256;  }
    else                 { W = Wo; WT = woT; K = 1024; bid -= 1280; }
    int k0 = (bid >> 4) * 32, n0 = (bid & 15) * 32;
    int x = threadIdx.x & 31, y = threadIdx.x >> 5;
#pragma unroll
    for (int i = 0; i < 32; i += 8)
        t[y + i][x] = W[(long)(k0 + y + i) * 512 + n0 + x];
    __syncthreads();
#pragma unroll
    for (int i = 0; i < 32; i += 8) {
        float v = t[x][y + i];
        asm("cvt.rna.tf32.f32 %0, %0;" : "+f"(v));
        WT[(long)(n0 + y + i) * K + k0 + x] = v;
    }
}

// ---------------------------------------------------------------------------
// initAll: pre-bias every GEMM destination; zero the scores accumulator.
//   out <- bo (131072 f4), qbuf <- bq (131072), keybuf <- bs (204800),
//   scores <- 0 (51200).  Total 518144 float4 -> grid 2024 x 256.
// ---------------------------------------------------------------------------
__global__ __launch_bounds__(256) void initAll(
    float* __restrict__ out, const float* __restrict__ bo,
    float* __restrict__ qb,  const float* __restrict__ bq,
    float* __restrict__ kb,  const float* __restrict__ bs,
    float* __restrict__ sc)
{
    int i = blockIdx.x * 256 + threadIdx.x;
    if (i < 131072) { ((float4*)out)[i] = ((const float4*)bo)[i & 127]; return; }
    i -= 131072;
    if (i < 131072) { ((float4*)qb)[i] = ((const float4*)bq)[i & 127]; return; }
    i -= 131072;
    if (i < 204800) { ((float4*)kb)[i] = ((const float4*)bs)[i & 127]; return; }
    i -= 204800;
    if (i < 51200) { float4 z = {0.f, 0.f, 0.f, 0.f}; ((float4*)sc)[i] = z; }
}

// ---------------------------------------------------------------------------
// tf32 mma.sync GEMM with split-K: C[M,512] += A @ WT^T  (C pre-biased)
//   CTA tile 64x64, BK=32, 128 threads, 3-stage cp.async pipeline, 48KB smem.
//   Grid = tiles * kSplit per descriptor; epilogue always atomicAdd.
// ---------------------------------------------------------------------------
struct GD {
    const float* A0; const float* A1;
    int rowSplit;
    int lda;
    const float* WT;
    int ldw;
    float* C;
    int Ktot;
    int Mreal;
    int tiles;      // (M/64) * 8
    int kSplit;
};

#define STG_BYTES 16384u
#define ABASE(s) ((s) * STG_BYTES)
#define BBASE(s) ((s) * STG_BYTES + 8192u)
#define DSMEM_G  49152

__global__ __launch_bounds__(128) void gemm_mma(GD ga, GD gb, int ctasA)
{
    GD g; int lbid;
    if (blockIdx.x < (unsigned)ctasA) { g = ga; lbid = blockIdx.x; }
    else                              { g = gb; lbid = blockIdx.x - ctasA; }

    const int within = lbid % g.tiles;
    const int kz     = lbid / g.tiles;
    const int Kslice = g.Ktot / g.kSplit;
    const int kOff   = kz * Kslice;

    const int bm = (within >> 3) * 64;     // tilesN = 8
    const int bn = (within & 7) * 64;
    const int tid  = threadIdx.x;
    const int lane = tid & 31;
    const int wid  = tid >> 5;
    const int wm   = (wid & 1) * 32;
    const int wn   = (wid >> 1) * 32;
    const int T = Kslice >> 5;
    const int Mlast = g.Mreal - 1;

    const uint32_t smem = s2u(dynsm);

    const int lr     = lane & 7;
    const int rowoff = ((lane >> 3) & 1) * 8;
    const int coff   = lane >> 4;
    const int arow   = wm + rowoff + lr;
    const int brow   = wn + rowoff + lr;

    float acc[2][4][4];
#pragma unroll
    for (int mi = 0; mi < 2; mi++)
#pragma unroll
        for (int ni = 0; ni < 4; ni++)
#pragma unroll
            for (int j = 0; j < 4; j++) acc[mi][ni][j] = 0.f;

    auto issue_tile = [&](int t, int s) {
        const int k0 = kOff + (t << 5);
#pragma unroll
        for (int i = 0; i < 4; i++) {
            int idx = tid + (i << 7);
            int r = idx >> 3, c = idx & 7;
            uint32_t dst = smem + ABASE(s) + (uint32_t)((r << 3) + (c ^ (r & 7))) * 16u;
            int gr = bm + r; if (gr > Mlast) gr = Mlast;
            const float* p = (gr < g.rowSplit)
                ? g.A0 + (long)gr * g.lda
                : g.A1 + (long)(gr - g.rowSplit) * g.lda;
            cp16(dst, p + k0 + c * 4);
        }
#pragma unroll
        for (int i = 0; i < 4; i++) {
            int idx = tid + (i << 7);
            int r = idx >> 3, c = idx & 7;
            uint32_t dst = smem + BBASE(s) + (uint32_t)((r << 3) + (c ^ (r & 7))) * 16u;
            cp16(dst, g.WT + (long)(bn + r) * g.ldw + k0 + c * 4);
        }
    };

    issue_tile(0, 0); CP_COMMIT();
    issue_tile(1, 1); CP_COMMIT();

    int s = 0;
    for (int t = 0; t < T; t++) {
        CP_WAITG(1);
        __syncthreads();
        int sn = s + 2; if (sn >= 3) sn -= 3;
        if (t + 2 < T) issue_tile(t + 2, sn);
        CP_COMMIT();

        const uint32_t ab = smem + ABASE(s);
        const uint32_t bb = smem + BBASE(s);
#pragma unroll
        for (int ks = 0; ks < 4; ks++) {
            uint32_t a[2][4], bf[2][4];
#pragma unroll
            for (int mi = 0; mi < 2; mi++) {
                uint32_t ad = ab + (uint32_t)(arow + mi * 16) * 128u
                                 + (uint32_t)(((ks << 1) + coff) ^ lr) * 16u;
                LDSM4(a[mi], ad);
            }
#pragma unroll
            for (int ng = 0; ng < 2; ng++) {
                uint32_t bd = bb + (uint32_t)(brow + ng * 16) * 128u
                                 + (uint32_t)(((ks << 1) + coff) ^ lr) * 16u;
                LDSM4(bf[ng], bd);
            }
#pragma unroll
            for (int mi = 0; mi < 2; mi++)
#pragma unroll
                for (int j = 0; j < 4; j++)
                    asm("cvt.rna.tf32.f32 %0, %0;" : "+r"(a[mi][j]));
#pragma unroll
            for (int mi = 0; mi < 2; mi++)
#pragma unroll
                for (int ni = 0; ni < 4; ni++) {
                    int ng = ni >> 1, sel = ni & 1;
                    MMA_TF32(acc[mi][ni], a[mi], bf[ng][sel], bf[ng][sel + 2]);
                }
        }
        if (++s >= 3) s -= 3;
    }

    // epilogue: atomic accumulation (C pre-biased)
    const int r0 = bm + wm + (lane >> 2);
    const int cb = bn + wn + 2 * (lane & 3);
#pragma unroll
    for (int ni = 0; ni < 4; ni++) {
        int col = cb + ni * 8;
#pragma unroll
        for (int mi = 0; mi < 2; mi++) {
            int r = r0 + mi * 16;
            if (r < g.Mreal) {
                atomicAdd(&g.C[(long)r * 512 + col],     acc[mi][ni][0]);
                atomicAdd(&g.C[(long)r * 512 + col + 1], acc[mi][ni][1]);
            }
            if (r + 8 < g.Mreal) {
                atomicAdd(&g.C[(long)(r + 8) * 512 + col],     acc[mi][ni][2]);
                atomicAdd(&g.C[(long)(r + 8) * 512 + col + 1], acc[mi][ni][3]);
            }
        }
    }
}

// ---------------------------------------------------------------------------
// attn_scores: partial qs/qt dots, split-K over z (2 halves of 256 k each).
//   Grid (16 lt, 8 b, 2 kz), 512 threads. atomicAdd into g_sc[b][l][j] (zeroed).
// Dyn smem: q[8*256] | kbuf[2][200*36]  = (2048 + 14400)*4 = 65792 B
// ---------------------------------------------------------------------------
#define DSMEM_S ((2048 + 14400) * 4)

__global__ __launch_bounds__(512) void attn_scores(
    const float* __restrict__ gq, const float* __restrict__ gkey,
    float* __restrict__ gsc)
{
    float* qsm = dynsm;
    float* kb  = dynsm + 2048;

    const int b  = blockIdx.y;
    const int l0 = blockIdx.x * 8;
    const int kbase = blockIdx.z * 256;
    const int tid = threadIdx.x;

    const float* keyS = gkey + (long)(b * SS) * HD;
    const float* keyT = gkey + (long)(BB * SS + b * TT) * HD;

    // load q slice (8 x 256): one float4 per thread
    {
        int l = tid >> 6, c4 = tid & 63;
        ((float4*)qsm)[l * 64 + c4] =
            __ldg((const float4*)(gq + (long)(b * LL + l0 + l) * HD + kbase) + c4);
    }

    const uint32_t kbu = s2u(kb);
    auto issue = [&](int t, int s) {
        const int k0 = kbase + (t << 5);
        for (int i = tid; i < 1600; i += 512) {
            int r = i >> 3, c4 = i & 7;
            uint32_t dst = kbu + (uint32_t)(s * 28800 + r * 144 + c4 * 16);
            const float* p = (r < SS) ? keyS + (long)r * HD
                                      : keyT + (long)(r - SS) * HD;
            cp16(dst, p + k0 + c4 * 4);
        }
    };

    const int j = tid >> 1;
    const int h = tid & 1;

    float acc[8];
#pragma unroll
    for (int l = 0; l < 8; l++) acc[l] = 0.f;

    issue(0, 0); CP_COMMIT();
    int buf = 0;
    for (int t = 0; t < 8; t++) {
        if (t + 1 < 8) { issue(t + 1, buf ^ 1); CP_COMMIT(); CP_WAITG(1); }
        else           { CP_WAITG(0); }
        __syncthreads();
        if (j < 200) {
            const float* kr = kb + buf * 7200 + j * 36 + h * 16;
            const float* qp = qsm + t * 32 + h * 16;
#pragma unroll
            for (int k4 = 0; k4 < 4; k4++) {
                float4 kv = *(const float4*)(kr + k4 * 4);
#pragma unroll
                for (int l = 0; l < 8; l++) {
                    float4 q4 = *(const float4*)(qp + l * 256 + k4 * 4);
                    acc[l] += kv.x * q4.x + kv.y * q4.y + kv.z * q4.z + kv.w * q4.w;
                }
            }
        }
        __syncthreads();
        buf ^= 1;
    }

#pragma unroll
    for (int l = 0; l < 8; l++) {
        float v = acc[l] + __shfl_xor_sync(0xffffffffu, acc[l], 1);
        if (h == 0 && j < 200)
            atomicAdd(&gsc[(long)(b * LL + l0 + l) * 200 + j], v);
    }
}

// ---------------------------------------------------------------------------
// attn_softmax: warp per (b,l) row. Reads g_sc, writes signed weights g_wts.
// ---------------------------------------------------------------------------
__global__ __launch_bounds__(256) void attn_softmax(
    const float* __restrict__ gsc, float* __restrict__ gwts)
{
    const int r = blockIdx.x * 8 + (threadIdx.x >> 5);    // 0..1023
    const int lane = threadIdx.x & 31;
    const int b = r >> 7, l = r & 127;
    const float* srow = gsc + (long)r * 200;
    float* wrow = gwts + (long)b * 200 * 128 + l;

    const float sc1 = 1.0f / 32.0f;
    const float rs2 = 0.70710678118654752f;

    float vb[4], m = -1e30f;
#pragma unroll
    for (int ii = 0; ii < 4; ii++) {
        int jj = lane + 32 * ii;
        vb[ii] = (jj < SS) ? srow[jj] * sc1 : -1e30f;
        m = fmaxf(m, vb[ii]);
    }
#pragma unroll
    for (int off = 16; off; off >>= 1) m = fmaxf(m, __shfl_xor_sync(0xffffffffu, m, off));
    float sum = 0.f;
#pragma unroll
    for (int ii = 0; ii < 4; ii++) {
        int jj = lane + 32 * ii;
        if (jj < SS) { vb[ii] = __expf(vb[ii] - m); sum += vb[ii]; }
    }
#pragma unroll
    for (int off = 16; off; off >>= 1) sum += __shfl_xor_sync(0xffffffffu, sum, off);
    float inv = rs2 / sum;
#pragma unroll
    for (int ii = 0; ii < 4; ii++) {
        int jj = lane + 32 * ii;
        if (jj < SS) wrow[(long)jj * 128] = vb[ii] * inv;
    }

    m = -1e30f;
#pragma unroll
    for (int ii = 0; ii < 4; ii++) {
        int jj = lane + 32 * ii;
        vb[ii] = (jj < TT) ? -srow[SS + jj] * sc1 : -1e30f;
        m = fmaxf(m, vb[ii]);
    }
#pragma unroll
    for (int off = 16; off; off >>= 1) m = fmaxf(m, __shfl_xor_sync(0xffffffffu, m, off));
    sum = 0.f;
#pragma unroll
    for (int ii = 0; ii < 4; ii++) {
        int jj = lane + 32 * ii;
        if (jj < TT) { vb[ii] = __expf(vb[ii] - m); sum += vb[ii]; }
    }
#pragma unroll
    for (int off = 16; off; off >>= 1) sum += __shfl_xor_sync(0xffffffffu, sum, off);
    inv = -rs2 / sum;                         // minus folded in
#pragma unroll
    for (int ii = 0; ii < 4; ii++) {
        int jj = lane + 32 * ii;
        if (jj < TT) wrow[(long)(SS + jj) * 128] = vb[ii] * inv;
    }
}

// ---------------------------------------------------------------------------
// attn_ctx: ctx[b, l0..l0+32, c0..c0+64] = sum_j w[j][l] * key[j][c]
// ---------------------------------------------------------------------------
__global__ __launch_bounds__(256) void attn_ctx(
    const float* __restrict__ gwts, const float* __restrict__ gkey,
    float* __restrict__ gctx)
{
    __shared__ __align__(16) float ws[200 * 36];

    const int c0 = blockIdx.x * 64;
    const int l0 = blockIdx.y * 32;
    const int b  = blockIdx.z;
    const int tid = threadIdx.x;

    for (int i = tid; i < 1600; i += 256) {
        int r = i >> 3, c4 = i & 7;
        *(float4*)&ws[r * 36 + c4 * 4] =
            *(const float4*)(gwts + ((long)b * 200 + r) * 128 + l0 + c4 * 4);
    }
    __syncthreads();

    const int ci = tid & 15;
    const int lg = tid >> 4;
    const float* pS = gkey + (long)(b * SS) * HD + c0 + ci * 4;
    const float* pT = gkey + (long)(BB * SS + b * TT) * HD + c0 + ci * 4;

    float4 a0 = {0,0,0,0}, a1 = {0,0,0,0};
#pragma unroll 4
    for (int jj = 0; jj < SS; jj++) {
        float4 kv = __ldg((const float4*)(pS + (long)jj * HD));
        float w0 = ws[jj * 36 + lg * 2];
        float w1 = ws[jj * 36 + lg * 2 + 1];
        a0.x += w0 * kv.x; a0.y += w0 * kv.y; a0.z += w0 * kv.z; a0.w += w0 * kv.w;
        a1.x += w1 * kv.x; a1.y += w1 * kv.y; a1.z += w1 * kv.z; a1.w += w1 * kv.w;
    }
#pragma unroll 4
    for (int jj = 0; jj < TT; jj++) {
        float4 kv = __ldg((const float4*)(pT + (long)jj * HD));
        float w0 = ws[(SS + jj) * 36 + lg * 2];
        float w1 = ws[(SS + jj) * 36 + lg * 2 + 1];
        a0.x += w0 * kv.x; a0.y += w0 * kv.y; a0.z += w0 * kv.z; a0.w += w0 * kv.w;
        a1.x += w1 * kv.x; a1.y += w1 * kv.y; a1.z += w1 * kv.z; a1.w += w1 * kv.w;
    }

    float* base = gctx + (long)(b * LL + l0 + lg * 2) * HD + c0 + ci * 4;
    *(float4*)base        = a0;
    *(float4*)(base + HD) = a1;
}

// ---------------------------------------------------------------------------
extern "C" void kernel_launch(void* const* d_in, const int* in_sizes, int n_in,
                              void* d_out, int out_size)
{
    const float* query = (const float*)d_in[0];
    const float* src   = (const float*)d_in[1];
    const float* trg   = (const float*)d_in[2];
    const float* Wq    = (const float*)d_in[3];
    const float* bq    = (const float*)d_in[4];
    const float* Ws    = (const float*)d_in[5];
    const float* bs    = (const float*)d_in[6];
    const float* Wo    = (const float*)d_in[7];
    const float* bo    = (const float*)d_in[8];
    float* out = (float*)d_out;

    float *qbuf, *keybuf, *ctxbuf, *scbuf, *wtsbuf, *wqT, *wsT, *woT;
    cudaGetSymbolAddress((void**)&qbuf,   g_q);
    cudaGetSymbolAddress((void**)&keybuf, g_key);
    cudaGetSymbolAddress((void**)&ctxbuf, g_ctx);
    cudaGetSymbolAddress((void**)&scbuf,  g_sc);
    cudaGetSymbolAddress((void**)&wtsbuf, g_wts);
    cudaGetSymbolAddress((void**)&wqT,    g_wqT);
    cudaGetSymbolAddress((void**)&wsT,    g_wsT);
    cudaGetSymbolAddress((void**)&woT,    g_woT);

    cudaFuncSetAttribute(gemm_mma,    cudaFuncAttributeMaxDynamicSharedMemorySize, DSMEM_G);
    cudaFuncSetAttribute(attn_scores, cudaFuncAttributeMaxDynamicSharedMemorySize, DSMEM_S);

    // Weight transposes (tf32 RN) + bias pre-init of all GEMM outputs + score zero
    transposeAll<<<1792, 256>>>(Wq, wqT, Ws, wsT, Wo, woT);
    initAll<<<2024, 256>>>(out, bo, qbuf, bq, keybuf, bs, scbuf);

    // Fused key-proj + q-proj, both split-K x2
    // key: M=1600 (25 mtiles), K=2048 -> 200 tiles x 2 = 400 CTAs
    // q:   M=1024 (16 mtiles), K=512  -> 128 tiles x 2 = 256 CTAs
    GD dKey = { src,   trg,   BB * SS, FD, wsT, FD, keybuf, FD, BB * (SS + TT), 200, 2 };
    GD dQ   = { query, query, 1 << 30, QD, wqT, QD, qbuf,   QD, BB * LL,        128, 2 };
    gemm_mma<<<400 + 256, 128, DSMEM_G>>>(dKey, dQ, 400);

    // Attention middle: split-K scores -> softmax -> ctx
    attn_scores<<<dim3(16, 8, 2), 512, DSMEM_S>>>(qbuf, keybuf, scbuf);
    attn_softmax<<<128, 256>>>(scbuf, wtsbuf);
    attn_ctx<<<dim3(8, 4, 8), 256>>>(wtsbuf, keybuf, ctxbuf);

    // Out-proj: concat split + split-K x2 each -> 512 CTAs
    GD dO1 = { query,  query,  1 << 30, QD, woT,      QD + HD, out, QD, BB * LL, 128, 2 };
    GD dO2 = { ctxbuf, ctxbuf, 1 << 30, HD, woT + QD, QD + HD, out, HD, BB * LL, 128, 2 };
    gemm_mma<<<512, 128, DSMEM_G>>>(dO1, dO2, 256);
}

// round 10
// speedup vs baseline: 1.4410x; 1.3903x over previous
#include <cuda_runtime.h>
#include <cstdint>
#include <math.h>

// Problem constants
#define BB   8
#define LL   128
#define SS   100
#define TT   100
#define QD   512
#define FD   2048
#define HD   512
#define OD   512

#define KP   224          // padded K for ctx gemm (200 -> 224)

// Scratch (device globals; no allocation APIs allowed)
__device__ float g_q[BB * LL * HD];
__device__ float g_key[BB * (SS + TT) * HD];
__device__ float g_keyT[BB * HD * KP];        // [b][c][j], pads stay 0
__device__ float g_ctx[BB * LL * HD];
__device__ float g_sc[BB * LL * 256];         // scores, 256-stride
__device__ float g_wts[BB * LL * KP];         // [b][l][j], pads zeroed
__device__ float g_wqT[HD * QD];
__device__ float g_wsT[HD * FD];
__device__ float g_woT[OD * (QD + HD)];

// ---------------------------------------------------------------------------
__device__ __forceinline__ uint32_t s2u(const void* p) {
    uint32_t a;
    asm("{ .reg .u64 t; cvta.to.shared.u64 t, %1; cvt.u32.u64 %0, t; }" : "=r"(a) : "l"(p));
    return a;
}
__device__ __forceinline__ void cp16(uint32_t dst, const void* src) {
    asm volatile("cp.async.cg.shared.global [%0], [%1], 16;" :: "r"(dst), "l"(src));
}
#define CP_COMMIT()  asm volatile("cp.async.commit_group;" ::: "memory")
#define CP_WAITG(n)  asm volatile("cp.async.wait_group %0;" :: "n"(n) : "memory")

#define LDSM4(r, a) \
    asm volatile("ldmatrix.sync.aligned.m8n8.x4.shared.b16 {%0,%1,%2,%3}, [%4];" \
        : "=r"((r)[0]), "=r"((r)[1]), "=r"((r)[2]), "=r"((r)[3]) : "r"(a))

#define MMA_TF32(d, a, b0, b1) \
    asm volatile("mma.sync.aligned.m16n8k8.row.col.f32.tf32.tf32.f32 " \
        "{%0,%1,%2,%3}, {%4,%5,%6,%7}, {%8,%9}, {%0,%1,%2,%3};" \
        : "+f"((d)[0]), "+f"((d)[1]), "+f"((d)[2]), "+f"((d)[3]) \
        : "r"((a)[0]), "r"((a)[1]), "r"((a)[2]), "r"((a)[3]), "r"(b0), "r"(b1))

extern __shared__ __align__(128) float dynsm[];

// ---------------------------------------------------------------------------
// prepAll: weight transposes (tf32 RN) + output pre-bias + accumulator zero.
//   bid < 1792 : transpose segments  (Wq 256 | Ws 1024 | Wo 512)
//   else       : init over 589824 float4
// ---------------------------------------------------------------------------
__global__ __launch_bounds__(256) void prepAll(
    const float* __restrict__ Wq, float* __restrict__ wqT,
    const float* __restrict__ Ws, float* __restrict__ wsT,
    const float* __restrict__ Wo, float* __restrict__ woT,
    float* __restrict__ out, const float* __restrict__ bo,
    float* __restrict__ qb,  const float* __restrict__ bq,
    float* __restrict__ kb,  const float* __restrict__ bs,
    float* __restrict__ sc,  float* __restrict__ wts)
{
    int bid = blockIdx.x;
    if (bid < 1792) {
        __shared__ float t[32][33];
        const float* W; float* WT; int K;
        if (bid < 256)       { W = Wq; WT = wqT; K = 512;  }
        else if (bid < 1280) { W = Ws; WT = wsT; K = 2048; bid -= 256;  }
        else                 { W = Wo; WT = woT; K = 1024; bid -= 1280; }
        int k0 = (bid >> 4) * 32, n0 = (bid & 15) * 32;
        int x = threadIdx.x & 31, y = threadIdx.x >> 5;
#pragma unroll
        for (int i = 0; i < 32; i += 8)
            t[y + i][x] = W[(long)(k0 + y + i) * 512 + n0 + x];
        __syncthreads();
#pragma unroll
        for (int i = 0; i < 32; i += 8) {
            float v = t[x][y + i];
            asm("cvt.rna.tf32.f32 %0, %0;" : "+f"(v));
            WT[(long)(n0 + y + i) * K + k0 + x] = v;
        }
        return;
    }
    int i = (bid - 1792) * 256 + threadIdx.x;
    if (i < 131072) { ((float4*)out)[i] = ((const float4*)bo)[i & 127]; return; }
    i -= 131072;
    if (i < 131072) { ((float4*)qb)[i] = ((const float4*)bq)[i & 127]; return; }
    i -= 131072;
    if (i < 204800) { ((float4*)kb)[i] = ((const float4*)bs)[i & 127]; return; }
    i -= 204800;
    float4 z = {0.f, 0.f, 0.f, 0.f};
    if (i < 65536) { ((float4*)sc)[i] = z; return; }
    i -= 65536;
    if (i < 57344) ((float4*)wts)[i] = z;
}

// ---------------------------------------------------------------------------
// Generalized batched tf32 mma.sync GEMM:
//   per batch: C[Mreal, nt*64] (+)= A[Mreal, K] @ B[Nreal, K]^T
//   kSplit>1 -> atomicAdd into pre-initialized C; kSplit==1 -> direct store.
// ---------------------------------------------------------------------------
struct GD {
    const float* A0; const float* A1; int aSplit; int lda; int bsA;
    const float* B0; const float* B1; int bSplit; int ldb; int bsB;
    float* C; int ldc; int bsC;
    int Ktot; int kSplit;
    int Mreal; int Nreal;
    int mt; int nt; int batches;
};

#define STG_BYTES 16384u
#define ABASE(s) ((s) * STG_BYTES)
#define BBASE(s) ((s) * STG_BYTES + 8192u)
#define DSMEM_G  49152

__global__ __launch_bounds__(128) void gemm_mma(GD ga, GD gb, int ctasA)
{
    GD g; int lbid;
    if (blockIdx.x < (unsigned)ctasA) { g = ga; lbid = blockIdx.x; }
    else                              { g = gb; lbid = blockIdx.x - ctasA; }

    const int tilesTot = g.mt * g.nt * g.batches;
    const int within = lbid % tilesTot;
    const int kz     = lbid / tilesTot;
    const int batch  = within / (g.mt * g.nt);
    const int rem    = within % (g.mt * g.nt);
    const int bm = (rem / g.nt) * 64;
    const int bn = (rem % g.nt) * 64;

    const int Kslice = g.Ktot / g.kSplit;
    const int kOff   = kz * Kslice;
    const int T = Kslice >> 5;

    const int tid  = threadIdx.x;
    const int lane = tid & 31;
    const int wid  = tid >> 5;
    const int wm   = (wid & 1) * 32;
    const int wn   = (wid >> 1) * 32;

    const uint32_t smem = s2u(dynsm);

    const int lr     = lane & 7;
    const int rowoff = ((lane >> 3) & 1) * 8;
    const int coff   = lane >> 4;
    const int arow   = wm + rowoff + lr;
    const int brow   = wn + rowoff + lr;

    float acc[2][4][4];
#pragma unroll
    for (int mi = 0; mi < 2; mi++)
#pragma unroll
        for (int ni = 0; ni < 4; ni++)
#pragma unroll
            for (int j = 0; j < 4; j++) acc[mi][ni][j] = 0.f;

    auto issue_tile = [&](int t, int s) {
        const int k0 = kOff + (t << 5);
#pragma unroll
        for (int i = 0; i < 4; i++) {          // A tile
            int idx = tid + (i << 7);
            int r = idx >> 3, c = idx & 7;
            uint32_t dst = smem + ABASE(s) + (uint32_t)((r << 3) + (c ^ (r & 7))) * 16u;
            int gr = bm + r; if (gr >= g.Mreal) gr = g.Mreal - 1;
            const float* p = (gr < g.aSplit)
                ? g.A0 + (long)gr * g.lda
                : g.A1 + (long)(gr - g.aSplit) * g.lda;
            cp16(dst, p + (long)batch * g.bsA + k0 + c * 4);
        }
#pragma unroll
        for (int i = 0; i < 4; i++) {          // B tile
            int idx = tid + (i << 7);
            int r = idx >> 3, c = idx & 7;
            uint32_t dst = smem + BBASE(s) + (uint32_t)((r << 3) + (c ^ (r & 7))) * 16u;
            int gc = bn + r; if (gc >= g.Nreal) gc = g.Nreal - 1;
            const float* p = (gc < g.bSplit)
                ? g.B0 + (long)gc * g.ldb
                : g.B1 + (long)(gc - g.bSplit) * g.ldb;
            cp16(dst, p + (long)batch * g.bsB + k0 + c * 4);
        }
    };

    issue_tile(0, 0); CP_COMMIT();
    issue_tile(1, 1); CP_COMMIT();

    int s = 0;
    for (int t = 0; t < T; t++) {
        CP_WAITG(1);
        __syncthreads();
        int sn = s + 2; if (sn >= 3) sn -= 3;
        if (t + 2 < T) issue_tile(t + 2, sn);
        CP_COMMIT();

        const uint32_t ab = smem + ABASE(s);
        const uint32_t bb = smem + BBASE(s);
#pragma unroll
        for (int ks = 0; ks < 4; ks++) {
            uint32_t a[2][4], bf[2][4];
#pragma unroll
            for (int mi = 0; mi < 2; mi++) {
                uint32_t ad = ab + (uint32_t)(arow + mi * 16) * 128u
                                 + (uint32_t)(((ks << 1) + coff) ^ lr) * 16u;
                LDSM4(a[mi], ad);
            }
#pragma unroll
            for (int ng = 0; ng < 2; ng++) {
                uint32_t bd = bb + (uint32_t)(brow + ng * 16) * 128u
                                 + (uint32_t)(((ks << 1) + coff) ^ lr) * 16u;
                LDSM4(bf[ng], bd);
            }
#pragma unroll
            for (int mi = 0; mi < 2; mi++)
#pragma unroll
                for (int j = 0; j < 4; j++)
                    asm("cvt.rna.tf32.f32 %0, %0;" : "+r"(a[mi][j]));
#pragma unroll
            for (int mi = 0; mi < 2; mi++)
#pragma unroll
                for (int ni = 0; ni < 4; ni++) {
                    int ng = ni >> 1, sel = ni & 1;
                    MMA_TF32(acc[mi][ni], a[mi], bf[ng][sel], bf[ng][sel + 2]);
                }
        }
        if (++s >= 3) s -= 3;
    }

    float* Cb = g.C + (long)batch * g.bsC;
    const int r0 = bm + wm + (lane >> 2);
    const int cb = bn + wn + 2 * (lane & 3);
    if (g.kSplit == 1) {
#pragma unroll
        for (int ni = 0; ni < 4; ni++) {
            int col = cb + ni * 8;
#pragma unroll
            for (int mi = 0; mi < 2; mi++) {
                int r = r0 + mi * 16;
                if (r < g.Mreal) {
                    float2 v0 = { acc[mi][ni][0], acc[mi][ni][1] };
                    *(float2*)&Cb[(long)r * g.ldc + col] = v0;
                }
                if (r + 8 < g.Mreal) {
                    float2 v1 = { acc[mi][ni][2], acc[mi][ni][3] };
                    *(float2*)&Cb[(long)(r + 8) * g.ldc + col] = v1;
                }
            }
        }
    } else {
#pragma unroll
        for (int ni = 0; ni < 4; ni++) {
            int col = cb + ni * 8;
#pragma unroll
            for (int mi = 0; mi < 2; mi++) {
                int r = r0 + mi * 16;
                if (r < g.Mreal) {
                    atomicAdd(&Cb[(long)r * g.ldc + col],     acc[mi][ni][0]);
                    atomicAdd(&Cb[(long)r * g.ldc + col + 1], acc[mi][ni][1]);
                }
                if (r + 8 < g.Mreal) {
                    atomicAdd(&Cb[(long)(r + 8) * g.ldc + col],     acc[mi][ni][2]);
                    atomicAdd(&Cb[(long)(r + 8) * g.ldc + col + 1], acc[mi][ni][3]);
                }
            }
        }
    }
}

// ---------------------------------------------------------------------------
// postScores: [bid < 896] key transpose -> g_keyT[b][c][j] (j<200; pads stay 0)
//             [bid >= 896] softmax: g_sc -> signed weights g_wts[b][l][j]
// ---------------------------------------------------------------------------
__global__ __launch_bounds__(256) void postScores(
    const float* __restrict__ gkey, float* __restrict__ gkeyT,
    const float* __restrict__ gsc,  float* __restrict__ gwts)
{
    const int bid = blockIdx.x;
    if (bid < 896) {
        __shared__ float t[32][33];
        const int b  = bid / 112;
        const int rm = bid % 112;
        const int c0 = (rm / 7) * 32;
        const int j0 = (rm % 7) * 32;
        const int x = threadIdx.x & 31, y = threadIdx.x >> 5;
#pragma unroll
        for (int i = 0; i < 32; i += 8) {
            int j = j0 + y + i; if (j > 199) j = 199;
            int srow = (j < SS) ? b * SS + j : BB * SS + b * TT + (j - SS);
            t[y + i][x] = gkey[(long)srow * HD + c0 + x];
        }
        __syncthreads();
        if (j0 + x < 200) {
#pragma unroll
            for (int i = 0; i < 32; i += 8)
                gkeyT[(long)(b * HD + c0 + y + i) * KP + j0 + x] = t[x][y + i];
        }
        return;
    }

    // softmax: warp per row
    const int r = (bid - 896) * 8 + (threadIdx.x >> 5);
    const int lane = threadIdx.x & 31;
    const int b = r >> 7, l = r & 127;
    const float* srow = gsc + (long)r * 256;
    float* wrow = gwts + (long)(b * LL + l) * KP;

    const float sc1 = 1.0f / 32.0f;
    const float rs2 = 0.70710678118654752f;

    float vb[4], m = -1e30f;
#pragma unroll
    for (int ii = 0; ii < 4; ii++) {
        int jj = lane + 32 * ii;
        vb[ii] = (jj < SS) ? srow[jj] * sc1 : -1e30f;
        m = fmaxf(m, vb[ii]);
    }
#pragma unroll
    for (int off = 16; off; off >>= 1) m = fmaxf(m, __shfl_xor_sync(0xffffffffu, m, off));
    float sum = 0.f;
#pragma unroll
    for (int ii = 0; ii < 4; ii++) {
        int jj = lane + 32 * ii;
        if (jj < SS) { vb[ii] = __expf(vb[ii] - m); sum += vb[ii]; }
    }
#pragma unroll
    for (int off = 16; off; off >>= 1) sum += __shfl_xor_sync(0xffffffffu, sum, off);
    float inv = rs2 / sum;
#pragma unroll
    for (int ii = 0; ii < 4; ii++) {
        int jj = lane + 32 * ii;
        if (jj < SS) wrow[jj] = vb[ii] * inv;
    }

    m = -1e30f;
#pragma unroll
    for (int ii = 0; ii < 4; ii++) {
        int jj = lane + 32 * ii;
        vb[ii] = (jj < TT) ? -srow[SS + jj] * sc1 : -1e30f;
        m = fmaxf(m, vb[ii]);
    }
#pragma unroll
    for (int off = 16; off; off >>= 1) m = fmaxf(m, __shfl_xor_sync(0xffffffffu, m, off));
    sum = 0.f;
#pragma unroll
    for (int ii = 0; ii < 4; ii++) {
        int jj = lane + 32 * ii;
        if (jj < TT) { vb[ii] = __expf(vb[ii] - m); sum += vb[ii]; }
    }
#pragma unroll
    for (int off = 16; off; off >>= 1) sum += __shfl_xor_sync(0xffffffffu, sum, off);
    inv = -rs2 / sum;                         // minus folded in
#pragma unroll
    for (int ii = 0; ii < 4; ii++) {
        int jj = lane + 32 * ii;
        if (jj < TT) wrow[SS + jj] = vb[ii] * inv;
    }
}

// ---------------------------------------------------------------------------
extern "C" void kernel_launch(void* const* d_in, const int* in_sizes, int n_in,
                              void* d_out, int out_size)
{
    const float* query = (const float*)d_in[0];
    const float* src   = (const float*)d_in[1];
    const float* trg   = (const float*)d_in[2];
    const float* Wq    = (const float*)d_in[3];
    const float* bq    = (const float*)d_in[4];
    const float* Ws    = (const float*)d_in[5];
    const float* bs    = (const float*)d_in[6];
    const float* Wo    = (const float*)d_in[7];
    const float* bo    = (const float*)d_in[8];
    float* out = (float*)d_out;

    float *qbuf, *keybuf, *keyTbuf, *ctxbuf, *scbuf, *wtsbuf, *wqT, *wsT, *woT;
    cudaGetSymbolAddress((void**)&qbuf,    g_q);
    cudaGetSymbolAddress((void**)&keybuf,  g_key);
    cudaGetSymbolAddress((void**)&keyTbuf, g_keyT);
    cudaGetSymbolAddress((void**)&ctxbuf,  g_ctx);
    cudaGetSymbolAddress((void**)&scbuf,   g_sc);
    cudaGetSymbolAddress((void**)&wtsbuf,  g_wts);
    cudaGetSymbolAddress((void**)&wqT,     g_wqT);
    cudaGetSymbolAddress((void**)&wsT,     g_wsT);
    cudaGetSymbolAddress((void**)&woT,     g_woT);

    cudaFuncSetAttribute(gemm_mma, cudaFuncAttributeMaxDynamicSharedMemorySize, DSMEM_G);

    // prep: transposes + bias pre-init + zeroing (one launch)
    prepAll<<<1792 + 2304, 256>>>(Wq, wqT, Ws, wsT, Wo, woT,
                                  out, bo, qbuf, bq, keybuf, bs, scbuf, wtsbuf);

    // Fused key-proj + q-proj, split-K x2  (400 + 256 CTAs)
    GD dKey = { src, trg, BB * SS, FD, 0,   wsT, wsT, 1 << 30, FD, 0,
                keybuf, 512, 0,  FD, 2,  BB * (SS + TT), 512,  25, 8, 1 };
    GD dQ   = { query, query, 1 << 30, QD, 0,   wqT, wqT, 1 << 30, QD, 0,
                qbuf, 512, 0,  QD, 2,  BB * LL, 512,  16, 8, 1 };
    gemm_mma<<<656, 128, DSMEM_G>>>(dKey, dQ, 400);

    // scores: batched gemm, C[b][128][256] += q_b @ key_b^T, split-K x2
    GD dSc = { qbuf, qbuf, 1 << 30, HD, LL * HD,
               keybuf, keybuf + (long)BB * SS * HD, SS, HD, SS * HD,
               scbuf, 256, LL * 256,  HD, 2,  LL, SS + TT,  2, 4, BB };
    gemm_mma<<<128, 128, DSMEM_G>>>(dSc, dSc, 128);

    // key transpose + softmax (one launch)
    postScores<<<896 + 128, 256>>>(keybuf, keyTbuf, scbuf, wtsbuf);

    // ctx: batched gemm, C[b][128][512] = wts_b @ keyT_b^T, direct store
    GD dCtx = { wtsbuf, wtsbuf, 1 << 30, KP, LL * KP,
                keyTbuf, keyTbuf, 1 << 30, KP, HD * KP,
                ctxbuf, 512, LL * HD,  KP, 1,  LL, HD,  2, 8, BB };
    gemm_mma<<<128, 128, DSMEM_G>>>(dCtx, dCtx, 128);

    // Out-proj: concat split + split-K x2 each (512 CTAs)
    GD dO1 = { query, query, 1 << 30, QD, 0,   woT, woT, 1 << 30, QD + HD, 0,
               out, 512, 0,  QD, 2,  BB * LL, 512,  16, 8, 1 };
    GD dO2 = { ctxbuf, ctxbuf, 1 << 30, HD, 0,   woT + QD, woT + QD, 1 << 30, QD + HD, 0,
               out, 512, 0,  HD, 2,  BB * LL, 512,  16, 8, 1 };
    gemm_mma<<<512, 128, DSMEM_G>>>(dO1, dO2, 256);
}

// round 11
// speedup vs baseline: 1.6989x; 1.1790x over previous
#include <cuda_runtime.h>
#include <cstdint>
#include <math.h>

// Problem constants
#define BB   8
#define LL   128
#define SS   100
#define TT   100
#define QD   512
#define FD   2048
#define HD   512
#define OD   512

#define KP   224          // padded K for ctx gemm (200 -> 224)

// Scratch (device globals; no allocation APIs allowed)
__device__ float g_q[BB * LL * HD];
__device__ float g_key[BB * (SS + TT) * HD];
__device__ float g_keyT[BB * HD * KP];        // [b][c][j], pads stay 0 (module-zeroed, never written)
__device__ float g_ctx[BB * LL * HD];
__device__ float g_sc[BB * LL * 256];         // scores, 256-stride
__device__ float g_wts[BB * LL * KP];         // [b][l][j], pads written 0 by softmax
__device__ float g_wqT[HD * QD];
__device__ float g_wsT[HD * FD];
__device__ float g_woT[OD * (QD + HD)];

// ---------------------------------------------------------------------------
__device__ __forceinline__ uint32_t s2u(const void* p) {
    uint32_t a;
    asm("{ .reg .u64 t; cvta.to.shared.u64 t, %1; cvt.u32.u64 %0, t; }" : "=r"(a) : "l"(p));
    return a;
}
__device__ __forceinline__ void cp16(uint32_t dst, const void* src) {
    asm volatile("cp.async.cg.shared.global [%0], [%1], 16;" :: "r"(dst), "l"(src));
}
#define CP_COMMIT()  asm volatile("cp.async.commit_group;" ::: "memory")
#define CP_WAITG(n)  asm volatile("cp.async.wait_group %0;" :: "n"(n) : "memory")

#define LDSM4(r, a) \
    asm volatile("ldmatrix.sync.aligned.m8n8.x4.shared.b16 {%0,%1,%2,%3}, [%4];" \
        : "=r"((r)[0]), "=r"((r)[1]), "=r"((r)[2]), "=r"((r)[3]) : "r"(a))

#define MMA_TF32(d, a, b0, b1) \
    asm volatile("mma.sync.aligned.m16n8k8.row.col.f32.tf32.tf32.f32 " \
        "{%0,%1,%2,%3}, {%4,%5,%6,%7}, {%8,%9}, {%0,%1,%2,%3};" \
        : "+f"((d)[0]), "+f"((d)[1]), "+f"((d)[2]), "+f"((d)[3]) \
        : "r"((a)[0]), "r"((a)[1]), "r"((a)[2]), "r"((a)[3]), "r"(b0), "r"(b1))

extern __shared__ __align__(128) float dynsm[];

// ---------------------------------------------------------------------------
// prepAll: weight transposes (tf32 RN) + keybuf pre-bias + scores zero.
//   bid < 1792       : transposes (Wq 256 | Ws 1024 | Wo 512)
//   1792..2592       : keybuf <- bs  (204800 f4)
//   2592..2848       : scbuf  <- 0   (65536 f4)
// ---------------------------------------------------------------------------
__global__ __launch_bounds__(256) void prepAll(
    const float* __restrict__ Wq, float* __restrict__ wqT,
    const float* __restrict__ Ws, float* __restrict__ wsT,
    const float* __restrict__ Wo, float* __restrict__ woT,
    float* __restrict__ kb, const float* __restrict__ bs,
    float* __restrict__ sc)
{
    int bid = blockIdx.x;
    if (bid < 1792) {
        __shared__ float t[32][33];
        const float* W; float* WT; int K;
        if (bid < 256)       { W = Wq; WT = wqT; K = 512;  }
        else if (bid < 1280) { W = Ws; WT = wsT; K = 2048; bid -= 256;  }
        else                 { W = Wo; WT = woT; K = 1024; bid -= 1280; }
        int k0 = (bid >> 4) * 32, n0 = (bid & 15) * 32;
        int x = threadIdx.x & 31, y = threadIdx.x >> 5;
#pragma unroll
        for (int i = 0; i < 32; i += 8)
            t[y + i][x] = W[(long)(k0 + y + i) * 512 + n0 + x];
        __syncthreads();
#pragma unroll
        for (int i = 0; i < 32; i += 8) {
            float v = t[x][y + i];
            asm("cvt.rna.tf32.f32 %0, %0;" : "+f"(v));
            WT[(long)(n0 + y + i) * K + k0 + x] = v;
        }
        return;
    }
    int i = (bid - 1792) * 256 + threadIdx.x;
    if (i < 204800) { ((float4*)kb)[i] = ((const float4*)bs)[i & 127]; return; }
    i -= 204800;
    if (i < 65536) { float4 z = {0.f, 0.f, 0.f, 0.f}; ((float4*)sc)[i] = z; }
}

// ---------------------------------------------------------------------------
// Generalized batched tf32 mma.sync GEMM (3 descriptors per launch):
//   per batch: C[Mreal, nt*64] (+)= A[Mreal, K] @ B[Nreal, K]^T [+ bias]
//   kSplit==1 -> direct store (+bias if given); kSplit>1 -> atomicAdd.
// ---------------------------------------------------------------------------
struct GD {
    const float* A0; const float* A1; int aSplit; int lda; int bsA;
    const float* B0; const float* B1; int bSplit; int ldb; int bsB;
    float* C; int ldc; int bsC;
    const float* bias;
    int Ktot; int kSplit;
    int Mreal; int Nreal;
    int mt; int nt; int batches;
};

#define STG_BYTES 16384u
#define ABASE(s) ((s) * STG_BYTES)
#define BBASE(s) ((s) * STG_BYTES + 8192u)
#define DSMEM_G  49152

__global__ __launch_bounds__(128) void gemm_mma(GD ga, GD gb, GD gc, int nA, int nAB)
{
    GD g; int lbid;
    if (blockIdx.x < (unsigned)nA)        { g = ga; lbid = blockIdx.x; }
    else if (blockIdx.x < (unsigned)nAB)  { g = gb; lbid = blockIdx.x - nA; }
    else                                  { g = gc; lbid = blockIdx.x - nAB; }

    const int tilesTot = g.mt * g.nt * g.batches;
    const int within = lbid % tilesTot;
    const int kz     = lbid / tilesTot;
    const int batch  = within / (g.mt * g.nt);
    const int rem    = within % (g.mt * g.nt);
    const int bm = (rem / g.nt) * 64;
    const int bn = (rem % g.nt) * 64;

    const int Kslice = g.Ktot / g.kSplit;
    const int kOff   = kz * Kslice;
    const int T = Kslice >> 5;

    const int tid  = threadIdx.x;
    const int lane = tid & 31;
    const int wid  = tid >> 5;
    const int wm   = (wid & 1) * 32;
    const int wn   = (wid >> 1) * 32;

    const uint32_t smem = s2u(dynsm);

    const int lr     = lane & 7;
    const int rowoff = ((lane >> 3) & 1) * 8;
    const int coff   = lane >> 4;
    const int arow   = wm + rowoff + lr;
    const int brow   = wn + rowoff + lr;

    float acc[2][4][4];
#pragma unroll
    for (int mi = 0; mi < 2; mi++)
#pragma unroll
        for (int ni = 0; ni < 4; ni++)
#pragma unroll
            for (int j = 0; j < 4; j++) acc[mi][ni][j] = 0.f;

    auto issue_tile = [&](int t, int s) {
        const int k0 = kOff + (t << 5);
#pragma unroll
        for (int i = 0; i < 4; i++) {          // A tile
            int idx = tid + (i << 7);
            int r = idx >> 3, c = idx & 7;
            uint32_t dst = smem + ABASE(s) + (uint32_t)((r << 3) + (c ^ (r & 7))) * 16u;
            int gr = bm + r; if (gr >= g.Mreal) gr = g.Mreal - 1;
            const float* p = (gr < g.aSplit)
                ? g.A0 + (long)gr * g.lda
                : g.A1 + (long)(gr - g.aSplit) * g.lda;
            cp16(dst, p + (long)batch * g.bsA + k0 + c * 4);
        }
#pragma unroll
        for (int i = 0; i < 4; i++) {          // B tile
            int idx = tid + (i << 7);
            int r = idx >> 3, c = idx & 7;
            uint32_t dst = smem + BBASE(s) + (uint32_t)((r << 3) + (c ^ (r & 7))) * 16u;
            int gc = bn + r; if (gc >= g.Nreal) gc = g.Nreal - 1;
            const float* p = (gc < g.bSplit)
                ? g.B0 + (long)gc * g.ldb
                : g.B1 + (long)(gc - g.bSplit) * g.ldb;
            cp16(dst, p + (long)batch * g.bsB + k0 + c * 4);
        }
    };

    issue_tile(0, 0); CP_COMMIT();
    issue_tile(1, 1); CP_COMMIT();

    int s = 0;
    for (int t = 0; t < T; t++) {
        CP_WAITG(1);
        __syncthreads();
        int sn = s + 2; if (sn >= 3) sn -= 3;
        if (t + 2 < T) issue_tile(t + 2, sn);
        CP_COMMIT();

        const uint32_t ab = smem + ABASE(s);
        const uint32_t bb = smem + BBASE(s);
#pragma unroll
        for (int ks = 0; ks < 4; ks++) {
            uint32_t a[2][4], bf[2][4];
#pragma unroll
            for (int mi = 0; mi < 2; mi++) {
                uint32_t ad = ab + (uint32_t)(arow + mi * 16) * 128u
                                 + (uint32_t)(((ks << 1) + coff) ^ lr) * 16u;
                LDSM4(a[mi], ad);
            }
#pragma unroll
            for (int ng = 0; ng < 2; ng++) {
                uint32_t bd = bb + (uint32_t)(brow + ng * 16) * 128u
                                 + (uint32_t)(((ks << 1) + coff) ^ lr) * 16u;
                LDSM4(bf[ng], bd);
            }
#pragma unroll
            for (int mi = 0; mi < 2; mi++)
#pragma unroll
                for (int j = 0; j < 4; j++)
                    asm("cvt.rna.tf32.f32 %0, %0;" : "+r"(a[mi][j]));
#pragma unroll
            for (int mi = 0; mi < 2; mi++)
#pragma unroll
                for (int ni = 0; ni < 4; ni++) {
                    int ng = ni >> 1, sel = ni & 1;
                    MMA_TF32(acc[mi][ni], a[mi], bf[ng][sel], bf[ng][sel + 2]);
                }
        }
        if (++s >= 3) s -= 3;
    }

    float* Cb = g.C + (long)batch * g.bsC;
    const int r0 = bm + wm + (lane >> 2);
    const int cb = bn + wn + 2 * (lane & 3);
    if (g.kSplit == 1) {
#pragma unroll
        for (int ni = 0; ni < 4; ni++) {
            int col = cb + ni * 8;
            float2 bv = {0.f, 0.f};
            if (g.bias) bv = *(const float2*)&g.bias[col];
#pragma unroll
            for (int mi = 0; mi < 2; mi++) {
                int r = r0 + mi * 16;
                if (r < g.Mreal) {
                    float2 v0 = { acc[mi][ni][0] + bv.x, acc[mi][ni][1] + bv.y };
                    *(float2*)&Cb[(long)r * g.ldc + col] = v0;
                }
                if (r + 8 < g.Mreal) {
                    float2 v1 = { acc[mi][ni][2] + bv.x, acc[mi][ni][3] + bv.y };
                    *(float2*)&Cb[(long)(r + 8) * g.ldc + col] = v1;
                }
            }
        }
    } else {
#pragma unroll
        for (int ni = 0; ni < 4; ni++) {
            int col = cb + ni * 8;
#pragma unroll
            for (int mi = 0; mi < 2; mi++) {
                int r = r0 + mi * 16;
                if (r < g.Mreal) {
                    atomicAdd(&Cb[(long)r * g.ldc + col],     acc[mi][ni][0]);
                    atomicAdd(&Cb[(long)r * g.ldc + col + 1], acc[mi][ni][1]);
                }
                if (r + 8 < g.Mreal) {
                    atomicAdd(&Cb[(long)(r + 8) * g.ldc + col],     acc[mi][ni][2]);
                    atomicAdd(&Cb[(long)(r + 8) * g.ldc + col + 1], acc[mi][ni][3]);
                }
            }
        }
    }
}

// ---------------------------------------------------------------------------
// postScores: [bid < 896] key transpose -> g_keyT[b][c][j] (j<200; pads stay 0)
//             [bid >= 896] softmax: g_sc -> signed weights g_wts[b][l][j]
// ---------------------------------------------------------------------------
__global__ __launch_bounds__(256) void postScores(
    const float* __restrict__ gkey, float* __restrict__ gkeyT,
    const float* __restrict__ gsc,  float* __restrict__ gwts)
{
    const int bid = blockIdx.x;
    if (bid < 896) {
        __shared__ float t[32][33];
        const int b  = bid / 112;
        const int rm = bid % 112;
        const int c0 = (rm / 7) * 32;
        const int j0 = (rm % 7) * 32;
        const int x = threadIdx.x & 31, y = threadIdx.x >> 5;
#pragma unroll
        for (int i = 0; i < 32; i += 8) {
            int j = j0 + y + i; if (j > 199) j = 199;
            int srow = (j < SS) ? b * SS + j : BB * SS + b * TT + (j - SS);
            t[y + i][x] = gkey[(long)srow * HD + c0 + x];
        }
        __syncthreads();
        if (j0 + x < 200) {
#pragma unroll
            for (int i = 0; i < 32; i += 8)
                gkeyT[(long)(b * HD + c0 + y + i) * KP + j0 + x] = t[x][y + i];
        }
        return;
    }

    // softmax: warp per row
    const int r = (bid - 896) * 8 + (threadIdx.x >> 5);
    const int lane = threadIdx.x & 31;
    const int b = r >> 7, l = r & 127;
    const float* srow = gsc + (long)r * 256;
    float* wrow = gwts + (long)(b * LL + l) * KP;

    const float sc1 = 1.0f / 32.0f;
    const float rs2 = 0.70710678118654752f;

    float vb[4], m = -1e30f;
#pragma unroll
    for (int ii = 0; ii < 4; ii++) {
        int jj = lane + 32 * ii;
        vb[ii] = (jj < SS) ? srow[jj] * sc1 : -1e30f;
        m = fmaxf(m, vb[ii]);
    }
#pragma unroll
    for (int off = 16; off; off >>= 1) m = fmaxf(m, __shfl_xor_sync(0xffffffffu, m, off));
    float sum = 0.f;
#pragma unroll
    for (int ii = 0; ii < 4; ii++) {
        int jj = lane + 32 * ii;
        if (jj < SS) { vb[ii] = __expf(vb[ii] - m); sum += vb[ii]; }
    }
#pragma unroll
    for (int off = 16; off; off >>= 1) sum += __shfl_xor_sync(0xffffffffu, sum, off);
    float inv = rs2 / sum;
#pragma unroll
    for (int ii = 0; ii < 4; ii++) {
        int jj = lane + 32 * ii;
        if (jj < SS) wrow[jj] = vb[ii] * inv;
    }

    m = -1e30f;
#pragma unroll
    for (int ii = 0; ii < 4; ii++) {
        int jj = lane + 32 * ii;
        vb[ii] = (jj < TT) ? -srow[SS + jj] * sc1 : -1e30f;
        m = fmaxf(m, vb[ii]);
    }
#pragma unroll
    for (int off = 16; off; off >>= 1) m = fmaxf(m, __shfl_xor_sync(0xffffffffu, m, off));
    sum = 0.f;
#pragma unroll
    for (int ii = 0; ii < 4; ii++) {
        int jj = lane + 32 * ii;
        if (jj < TT) { vb[ii] = __expf(vb[ii] - m); sum += vb[ii]; }
    }
#pragma unroll
    for (int off = 16; off; off >>= 1) sum += __shfl_xor_sync(0xffffffffu, sum, off);
    inv = -rs2 / sum;                         // minus folded in
#pragma unroll
    for (int ii = 0; ii < 4; ii++) {
        int jj = lane + 32 * ii;
        if (jj < TT)                 wrow[SS + jj] = vb[ii] * inv;
        else if (SS + jj < KP)       wrow[SS + jj] = 0.f;      // zero pads
    }
}

// ---------------------------------------------------------------------------
extern "C" void kernel_launch(void* const* d_in, const int* in_sizes, int n_in,
                              void* d_out, int out_size)
{
    const float* query = (const float*)d_in[0];
    const float* src   = (const float*)d_in[1];
    const float* trg   = (const float*)d_in[2];
    const float* Wq    = (const float*)d_in[3];
    const float* bq    = (const float*)d_in[4];
    const float* Ws    = (const float*)d_in[5];
    const float* bs    = (const float*)d_in[6];
    const float* Wo    = (const float*)d_in[7];
    const float* bo    = (const float*)d_in[8];
    float* out = (float*)d_out;

    float *qbuf, *keybuf, *keyTbuf, *ctxbuf, *scbuf, *wtsbuf, *wqT, *wsT, *woT;
    cudaGetSymbolAddress((void**)&qbuf,    g_q);
    cudaGetSymbolAddress((void**)&keybuf,  g_key);
    cudaGetSymbolAddress((void**)&keyTbuf, g_keyT);
    cudaGetSymbolAddress((void**)&ctxbuf,  g_ctx);
    cudaGetSymbolAddress((void**)&scbuf,   g_sc);
    cudaGetSymbolAddress((void**)&wtsbuf,  g_wts);
    cudaGetSymbolAddress((void**)&wqT,     g_wqT);
    cudaGetSymbolAddress((void**)&wsT,     g_wsT);
    cudaGetSymbolAddress((void**)&woT,     g_woT);

    cudaFuncSetAttribute(gemm_mma, cudaFuncAttributeMaxDynamicSharedMemorySize, DSMEM_G);

    // prep: transposes + keybuf pre-bias + scbuf zero
    prepAll<<<2848, 256>>>(Wq, wqT, Ws, wsT, Wo, woT, keybuf, bs, scbuf);

    // Launch 2: key-proj (ks2, atomic) + q-proj (ks1+bias) + out1 (ks1+bias)
    GD dKey = { src, trg, BB * SS, FD, 0,   wsT, wsT, 1 << 30, FD, 0,
                keybuf, 512, 0,  (const float*)0,  FD, 2,
                BB * (SS + TT), 512,  25, 8, 1 };
    GD dQ   = { query, query, 1 << 30, QD, 0,   wqT, wqT, 1 << 30, QD, 0,
                qbuf, 512, 0,  bq,  QD, 1,  BB * LL, 512,  16, 8, 1 };
    GD dO1  = { query, query, 1 << 30, QD, 0,   woT, woT, 1 << 30, QD + HD, 0,
                out, 512, 0,  bo,  QD, 1,  BB * LL, 512,  16, 8, 1 };
    gemm_mma<<<656, 128, DSMEM_G>>>(dKey, dQ, dO1, 400, 528);

    // scores: batched gemm, C[b][128][256] += q_b @ key_b^T, split-K x2
    GD dSc = { qbuf, qbuf, 1 << 30, HD, LL * HD,
               keybuf, keybuf + (long)BB * SS * HD, SS, HD, SS * HD,
               scbuf, 256, LL * 256,  (const float*)0,  HD, 2,
               LL, SS + TT,  2, 4, BB };
    gemm_mma<<<128, 128, DSMEM_G>>>(dSc, dSc, dSc, 128, 128);

    // key transpose + softmax
    postScores<<<896 + 128, 256>>>(keybuf, keyTbuf, scbuf, wtsbuf);

    // ctx: batched gemm, C[b][128][512] = wts_b @ keyT_b^T, direct store
    GD dCtx = { wtsbuf, wtsbuf, 1 << 30, KP, LL * KP,
                keyTbuf, keyTbuf, 1 << 30, KP, HD * KP,
                ctxbuf, 512, LL * HD,  (const float*)0,  KP, 1,
                LL, HD,  2, 8, BB };
    gemm_mma<<<128, 128, DSMEM_G>>>(dCtx, dCtx, dCtx, 128, 128);

    // out2: ctx @ Wo[512:], split-K x2, atomic into out (holds bias + out1)
    GD dO2 = { ctxbuf, ctxbuf, 1 << 30, HD, 0,
               woT + QD, woT + QD, 1 << 30, QD + HD, 0,
               out, 512, 0,  (const float*)0,  HD, 2,  BB * LL, 512,  16, 8, 1 };
    gemm_mma<<<256, 128, DSMEM_G>>>(dO2, dO2, dO2, 256, 256);
}